// round 15
// baseline (speedup 1.0000x reference)
#include <cuda_runtime.h>
#include <cuda_fp16.h>
#include <math.h>
#include <stdint.h>

#define D_MODEL 1024
#define S_LEN   2048
#define BATCH   2
#define HEADS   16
#define DEPTH   64
#define ROWS    (BATCH * S_LEN)     // 4096
#define BH      (BATCH * HEADS)     // 32

#define OUT_ELEMS  ((size_t)ROWS * D_MODEL)
#define ATTN_ELEMS ((size_t)BH * S_LEN * S_LEN)

__device__ __half g_xh[ROWS * D_MODEL];
__device__ __half g_wth[4 * D_MODEL * D_MODEL];   // transposed fp16 weights [n][k]
__device__ __half g_qh[ROWS * D_MODEL];
__device__ __half g_kh[ROWS * D_MODEL];
__device__ __half g_vh[ROWS * D_MODEL];
__device__ __half g_vt[ROWS * D_MODEL];           // V transposed per batch [d][s]
__device__ __half g_ch[ROWS * D_MODEL];           // ctx fp16
__device__ float  g_attn_scratch[ATTN_ELEMS];

// ---------------------------------------------------------------------------
#define CPA(dst, src) asm volatile("cp.async.cg.shared.global [%0], [%1], 16;" :: "r"(dst), "l"(src))
#define CPC()         asm volatile("cp.async.commit_group;")
#define CPW(n)        asm volatile("cp.async.wait_group %0;" :: "n"(n))

#define LDSM_X4(r0, r1, r2, r3, addr)                                            \
    asm volatile("ldmatrix.sync.aligned.m8n8.x4.shared.b16 {%0,%1,%2,%3}, [%4];" \
                 : "=r"(r0), "=r"(r1), "=r"(r2), "=r"(r3) : "r"(addr))

__device__ __forceinline__ void mma16(float* c, const uint32_t* a, const uint32_t* b) {
    asm volatile(
        "mma.sync.aligned.m16n8k16.row.col.f32.f16.f16.f32 "
        "{%0,%1,%2,%3}, {%4,%5,%6,%7}, {%8,%9}, {%0,%1,%2,%3};"
        : "+f"(c[0]), "+f"(c[1]), "+f"(c[2]), "+f"(c[3])
        : "r"(a[0]), "r"(a[1]), "r"(a[2]), "r"(a[3]), "r"(b[0]), "r"(b[1]));
}

__device__ __forceinline__ uint32_t sptr(const void* p) {
    return (uint32_t)__cvta_generic_to_shared(p);
}

// ---------------------------------------------------------------------------
__global__ void to_half_kernel(const float* __restrict__ in,
                               __half* __restrict__ out, int n4) {
    int i = blockIdx.x * blockDim.x + threadIdx.x;
    if (i < n4) {
        float4 v = ((const float4*)in)[i];
        __half2* o = (__half2*)(out + (size_t)i * 4);
        o[0] = __floats2half2_rn(v.x, v.y);
        o[1] = __floats2half2_rn(v.z, v.w);
    }
}

__global__ void transpose_half_w(const float* __restrict__ w0, const float* __restrict__ w1,
                                 const float* __restrict__ w2, const float* __restrict__ w3,
                                 __half* __restrict__ out) {
    __shared__ float tile[32][33];
    const float* in = blockIdx.z == 0 ? w0 : (blockIdx.z == 1 ? w1 :
                      (blockIdx.z == 2 ? w2 : w3));
    __half* o = out + (size_t)blockIdx.z * D_MODEL * D_MODEL;
    const int bx = blockIdx.x * 32, by = blockIdx.y * 32;
    const int tx = threadIdx.x, ty = threadIdx.y;
    #pragma unroll
    for (int i = 0; i < 32; i += 8)
        tile[ty + i][tx] = in[(size_t)(by + ty + i) * D_MODEL + bx + tx];
    __syncthreads();
    #pragma unroll
    for (int i = 0; i < 32; i += 8)
        o[(size_t)(bx + ty + i) * D_MODEL + by + tx] =
            __float2half_rn(tile[tx][ty + i]);
}

__global__ void transpose_v_half(const __half* __restrict__ v, __half* __restrict__ vt) {
    __shared__ __half tile[32][33];
    const int b = blockIdx.z;
    const int bx = blockIdx.x * 32;   // d
    const int by = blockIdx.y * 32;   // s
    const int tx = threadIdx.x, ty = threadIdx.y;
    #pragma unroll
    for (int i = 0; i < 32; i += 8)
        tile[ty + i][tx] = v[((size_t)b * S_LEN + by + ty + i) * D_MODEL + bx + tx];
    __syncthreads();
    #pragma unroll
    for (int i = 0; i < 32; i += 8)
        vt[((size_t)b * D_MODEL + bx + ty + i) * S_LEN + by + tx] = tile[tx][ty + i];
}

// ---------------------------------------------------------------------------
// fp16 NT GEMM + bias, up to 3 weight segments. ldmatrix fragment loads.
// BM=128 BN=128 BK=64(h), 3-stage cp.async. 8 warps (2x4), warp tile 64x32.
// ---------------------------------------------------------------------------
__global__ void __launch_bounds__(256, 2) gemm_h(
    const __half* __restrict__ A,
    const __half* __restrict__ B0, const __half* __restrict__ B1, const __half* __restrict__ B2,
    const float* __restrict__ bi0, const float* __restrict__ bi1, const float* __restrict__ bi2,
    __half* __restrict__ Ch0, __half* __restrict__ Ch1, __half* __restrict__ Ch2,
    float* __restrict__ Cf, int half_out) {
    extern __shared__ uint32_t smu[];
    uint32_t* Aw = smu;
    uint32_t* Bw = smu + 13824;

    const int sel = blockIdx.x >> 3;
    const __half* B   = sel == 0 ? B0  : (sel == 1 ? B1  : B2);
    const float* bias = sel == 0 ? bi0 : (sel == 1 ? bi1 : bi2);
    __half* Ch        = sel == 0 ? Ch0 : (sel == 1 ? Ch1 : Ch2);
    const int n0 = (blockIdx.x & 7) * 128;
    const int m0 = blockIdx.y * 128;

    const int tid = threadIdx.x, lane = tid & 31, warp = tid >> 5;
    const int wm = warp >> 2, wn = warp & 3;
    const int g = lane >> 2, tg = lane & 3;
    const int a_row = lane & 15, a_w = (lane >> 4) * 4;
    const int b_row = ((lane >> 4) << 3) + (lane & 7), b_w = ((lane >> 3) & 1) * 4;

    float acc[4][4][4] = {};

#define STAGE_G(kt, buf) {                                                       \
        _Pragma("unroll")                                                        \
        for (int i = 0; i < 4; i++) {                                            \
            int c = i * 256 + tid;                                               \
            int row = c >> 3, ch = c & 7;                                        \
            CPA(sptr(&Aw[(buf) * 4608 + row * 36 + ch * 4]),                     \
                A + (size_t)(m0 + row) * D_MODEL + (kt) + ch * 8);               \
            CPA(sptr(&Bw[(buf) * 4608 + row * 36 + ch * 4]),                     \
                B + (size_t)(n0 + row) * D_MODEL + (kt) + ch * 8);               \
        }                                                                        \
        CPC();                                                                   \
    }

    STAGE_G(0, 0);
    STAGE_G(64, 1);

    const int NT = D_MODEL / 64;
    for (int t = 0; t < NT; t++) {
        if (t + 1 < NT) { CPW(1); } else { CPW(0); }
        __syncthreads();
        if (t + 2 < NT) STAGE_G((t + 2) * 64, (t + 2) % 3);

        const uint32_t Ab = sptr(Aw + (t % 3) * 4608);
        const uint32_t Bb = sptr(Bw + (t % 3) * 4608);
        #pragma unroll
        for (int kk = 0; kk < 4; kk++) {
            const int kb = kk * 8;
            uint32_t a[4][4], b[4][2];
            #pragma unroll
            for (int mi = 0; mi < 4; mi++)
                LDSM_X4(a[mi][0], a[mi][1], a[mi][2], a[mi][3],
                        Ab + ((wm * 64 + mi * 16 + a_row) * 36 + kb + a_w) * 4);
            LDSM_X4(b[0][0], b[0][1], b[1][0], b[1][1],
                    Bb + ((wn * 32 + b_row) * 36 + kb + b_w) * 4);
            LDSM_X4(b[2][0], b[2][1], b[3][0], b[3][1],
                    Bb + ((wn * 32 + 16 + b_row) * 36 + kb + b_w) * 4);
            #pragma unroll
            for (int mi = 0; mi < 4; mi++)
                #pragma unroll
                for (int ni = 0; ni < 4; ni++)
                    mma16(acc[mi][ni], a[mi], b[ni]);
        }
    }
#undef STAGE_G

    #pragma unroll
    for (int mi = 0; mi < 4; mi++) {
        int r = m0 + wm * 64 + mi * 16 + g;
        #pragma unroll
        for (int ni = 0; ni < 4; ni++) {
            int c = n0 + wn * 32 + ni * 8 + 2 * tg;
            float b0 = bias[c], b1 = bias[c + 1];
            float v0 = acc[mi][ni][0] + b0;
            float v1 = acc[mi][ni][1] + b1;
            float v2 = acc[mi][ni][2] + b0;
            float v3 = acc[mi][ni][3] + b1;
            if (half_out) {
                *(__half2*)(Ch + (size_t)r * D_MODEL + c) = __floats2half2_rn(v0, v1);
                *(__half2*)(Ch + (size_t)(r + 8) * D_MODEL + c) = __floats2half2_rn(v2, v3);
            } else {
                *(float2*)(Cf + (size_t)r * D_MODEL + c) = make_float2(v0, v1);
                *(float2*)(Cf + (size_t)(r + 8) * D_MODEL + c) = make_float2(v2, v3);
            }
        }
    }
}

// ---------------------------------------------------------------------------
// Fused attention (fp16, recompute, ldmatrix): CTA = (bh, 128-q-strip), 512 thr.
// Pass 1: S=Q@K^T, rowsum of fp16(exp(S/8)) in registers.
// Pass 2: recompute S, stage fp16 P in smem, COALESCED normalized fp32 attn
//         write sourced from smem (512B per warp instruction), ctx=(P@V)*inv.
// Smem (words): Qs@0 (4608) | Kbuf@4608 (2x4608) | Vbuf@13824 (2x4352) |
//               Ps@22528 (8704) | red@31232 (512).  Total 126976 B.
// ---------------------------------------------------------------------------
__global__ void __launch_bounds__(512, 1) fused_attn(
    const __half* __restrict__ q, const __half* __restrict__ kmat,
    const __half* __restrict__ vt, float* __restrict__ attn,
    __half* __restrict__ ctx) {
    extern __shared__ uint32_t smu[];
    uint32_t* Qs = smu;
    float* red = (float*)(smu + 31232);

    const int bh = blockIdx.y;
    const int bb = bh >> 4, h = bh & 15;
    const __half* Qh = q    + (size_t)bb * S_LEN * D_MODEL + h * DEPTH;
    const __half* Kh = kmat + (size_t)bb * S_LEN * D_MODEL + h * DEPTH;
    const __half* Vp = vt + ((size_t)bb * D_MODEL + h * DEPTH) * S_LEN;
    const int q0 = blockIdx.x * 128;
    float* Ap = attn + (size_t)bh * S_LEN * S_LEN + (size_t)q0 * S_LEN;
    __half* Cp = ctx + (size_t)bb * S_LEN * D_MODEL + (size_t)q0 * D_MODEL + h * DEPTH;

    const int tid = threadIdx.x, lane = tid & 31, warp = tid >> 5;
    const int wmS = warp >> 2, wnS = warp & 3;     // 4x4, 32x32 tiles (S)
    const int wmP = warp >> 1, wnP = warp & 1;     // 8x2, 16x32 tiles (PV)
    const int g = lane >> 2, tg = lane & 3;
    const int a_row = lane & 15, a_w = (lane >> 4) * 4;
    const int b_row = ((lane >> 4) << 3) + (lane & 7), b_w = ((lane >> 3) & 1) * 4;

#define STAGE_Q() {                                                              \
        _Pragma("unroll")                                                        \
        for (int i = 0; i < 2; i++) {                                            \
            int c = i * 512 + tid;                                               \
            int row = c >> 3, ch = c & 7;                                        \
            CPA(sptr(&smu[row * 36 + ch * 4]),                                   \
                Qh + (size_t)(q0 + row) * D_MODEL + ch * 8);                     \
        }                                                                        \
    }
#define STAGE_K(t, buf) {                                                        \
        uint32_t* Kb_ = smu + 4608 + (buf) * 4608;                               \
        _Pragma("unroll")                                                        \
        for (int i = 0; i < 2; i++) {                                            \
            int c = i * 512 + tid;                                               \
            int row = c >> 3, ch = c & 7;                                        \
            CPA(sptr(&Kb_[row * 36 + ch * 4]),                                   \
                Kh + (size_t)((t) * 128 + row) * D_MODEL + ch * 8);              \
        }                                                                        \
    }
#define STAGE_V(t, buf) {                                                        \
        uint32_t* Vb_ = smu + 13824 + (buf) * 4352;                              \
        _Pragma("unroll")                                                        \
        for (int i = 0; i < 2; i++) {                                            \
            int c = i * 512 + tid;                                               \
            int row = c >> 4, ch = c & 15;                                       \
            CPA(sptr(&Vb_[row * 68 + ch * 4]),                                   \
                Vp + (size_t)row * S_LEN + (t) * 128 + ch * 8);                  \
        }                                                                        \
    }
// S-tile mma (ldmatrix): acc[2][4][4] += Q(32 rows) x K(32 cols), depth 64.
#define S_MMA(KbA, acc) {                                                        \
        _Pragma("unroll")                                                        \
        for (int kk = 0; kk < 4; kk++) {                                         \
            const int kb = kk * 8;                                               \
            uint32_t a[2][4], b[4][2];                                           \
            _Pragma("unroll")                                                    \
            for (int mi = 0; mi < 2; mi++)                                       \
                LDSM_X4(a[mi][0], a[mi][1], a[mi][2], a[mi][3],                  \
                        QsA + ((wmS * 32 + mi * 16 + a_row) * 36 + kb + a_w) * 4); \
            LDSM_X4(b[0][0], b[0][1], b[1][0], b[1][1],                          \
                    (KbA) + ((wnS * 32 + b_row) * 36 + kb + b_w) * 4);           \
            LDSM_X4(b[2][0], b[2][1], b[3][0], b[3][1],                          \
                    (KbA) + ((wnS * 32 + 16 + b_row) * 36 + kb + b_w) * 4);      \
            _Pragma("unroll")                                                    \
            for (int mi = 0; mi < 2; mi++)                                       \
                _Pragma("unroll")                                                \
                for (int ni = 0; ni < 4; ni++)                                   \
                    mma16(acc[mi][ni], a[mi], b[ni]);                            \
        }                                                                        \
    }

    const uint32_t QsA = sptr(Qs);

    // ---------------- Pass 1: row sums ----------------
    STAGE_Q(); STAGE_K(0, 0); CPC();

    float ps[4] = {0.f, 0.f, 0.f, 0.f};

    for (int t = 0; t < 16; t++) {
        CPW(0);
        __syncthreads();
        if (t + 1 < 16) { STAGE_K(t + 1, (t + 1) & 1); CPC(); }
        const uint32_t KbA = sptr(smu + 4608 + (t & 1) * 4608);

        float acc[2][4][4] = {};
        S_MMA(KbA, acc);

        #pragma unroll
        for (int mi = 0; mi < 2; mi++)
            #pragma unroll
            for (int ni = 0; ni < 4; ni++) {
                __half2 h01 = __floats2half2_rn(__expf(acc[mi][ni][0] * 0.125f),
                                                __expf(acc[mi][ni][1] * 0.125f));
                __half2 h23 = __floats2half2_rn(__expf(acc[mi][ni][2] * 0.125f),
                                                __expf(acc[mi][ni][3] * 0.125f));
                float2 f01 = __half22float2(h01);
                float2 f23 = __half22float2(h23);
                ps[mi * 2]     += f01.x + f01.y;
                ps[mi * 2 + 1] += f23.x + f23.y;
            }
        __syncthreads();
    }

    #pragma unroll
    for (int j = 0; j < 4; j++) {
        ps[j] += __shfl_xor_sync(0xffffffffu, ps[j], 1);
        ps[j] += __shfl_xor_sync(0xffffffffu, ps[j], 2);
    }
    if (tg == 0) {
        int rbase = wmS * 32 + g;
        red[wnS * 128 + rbase]      = ps[0];
        red[wnS * 128 + rbase + 8]  = ps[1];
        red[wnS * 128 + rbase + 16] = ps[2];
        red[wnS * 128 + rbase + 24] = ps[3];
    }
    __syncthreads();
    if (tid < 128) {
        float s = red[tid] + red[128 + tid] + red[256 + tid] + red[384 + tid];
        red[tid] = 1.0f / s;
    }
    __syncthreads();

    // ---------------- Pass 2: attn write + P@V ----------------
    uint32_t* Ps = smu + 22528;
    const uint32_t PsA = sptr(Ps);
    STAGE_K(0, 0); STAGE_V(0, 0); CPC();

    float accPV[4][4] = {};

    for (int t = 0; t < 16; t++) {
        CPW(0);
        __syncthreads();
        if (t + 1 < 16) { STAGE_K(t + 1, (t + 1) & 1); STAGE_V(t + 1, (t + 1) & 1); CPC(); }
        const uint32_t KbA = sptr(smu + 4608 + (t & 1) * 4608);
        const uint32_t VbA = sptr(smu + 13824 + (t & 1) * 4352);

        float acc[2][4][4] = {};
        S_MMA(KbA, acc);

        // exp (identical to pass 1), stage fp16 P into smem.
        #pragma unroll
        for (int mi = 0; mi < 2; mi++) {
            int r = wmS * 32 + mi * 16 + g;
            #pragma unroll
            for (int ni = 0; ni < 4; ni++) {
                __half2 h01 = __floats2half2_rn(__expf(acc[mi][ni][0] * 0.125f),
                                                __expf(acc[mi][ni][1] * 0.125f));
                __half2 h23 = __floats2half2_rn(__expf(acc[mi][ni][2] * 0.125f),
                                                __expf(acc[mi][ni][3] * 0.125f));
                Ps[r * 68 + wnS * 16 + ni * 4 + tg] = *(const uint32_t*)&h01;
                Ps[(r + 8) * 68 + wnS * 16 + ni * 4 + tg] = *(const uint32_t*)&h23;
            }
        }
        __syncthreads();   // Ps staged

        // Coalesced normalized attn write: each warp instruction stores one
        // full 128-col row segment (32 lanes x 16B = 512B contiguous).
        #pragma unroll
        for (int i = 0; i < 8; i++) {
            int r = i * 16 + warp;
            float inv = red[r];
            const uint32_t* src = Ps + r * 68 + lane * 2;
            float2 f0 = __half22float2(*(const __half2*)&src[0]);
            float2 f1 = __half22float2(*(const __half2*)&src[1]);
            *(float4*)(Ap + (size_t)r * S_LEN + t * 128 + lane * 4) =
                make_float4(f0.x * inv, f0.y * inv, f1.x * inv, f1.y * inv);
        }

        // PV: accPV += P_tile(128x128) @ V_tile(64x128)^T  (8x2 warps, 16x32)
        #pragma unroll
        for (int kk = 0; kk < 8; kk++) {
            const int kb = kk * 8;
            uint32_t a[4], b[4][2];
            LDSM_X4(a[0], a[1], a[2], a[3],
                    PsA + ((wmP * 16 + a_row) * 68 + kb + a_w) * 4);
            LDSM_X4(b[0][0], b[0][1], b[1][0], b[1][1],
                    VbA + ((wnP * 32 + b_row) * 68 + kb + b_w) * 4);
            LDSM_X4(b[2][0], b[2][1], b[3][0], b[3][1],
                    VbA + ((wnP * 32 + 16 + b_row) * 68 + kb + b_w) * 4);
            #pragma unroll
            for (int ni = 0; ni < 4; ni++)
                mma16(accPV[ni], a, b[ni]);
        }
        __syncthreads();   // PV + write reads done before Ps overwrite
    }

    // Epilogue: ctx = accPV * inv -> fp16.
    {
        int rp = wmP * 16 + g;
        float invA = red[rp], invB = red[rp + 8];
        #pragma unroll
        for (int ni = 0; ni < 4; ni++) {
            int c = wnP * 32 + ni * 8 + 2 * tg;
            *(__half2*)(Cp + (size_t)rp * D_MODEL + c) =
                __floats2half2_rn(accPV[ni][0] * invA, accPV[ni][1] * invA);
            *(__half2*)(Cp + (size_t)(rp + 8) * D_MODEL + c) =
                __floats2half2_rn(accPV[ni][2] * invB, accPV[ni][3] * invB);
        }
    }
#undef STAGE_Q
#undef STAGE_K
#undef STAGE_V
#undef S_MMA
}

// ---------------------------------------------------------------------------
extern "C" void kernel_launch(void* const* d_in, const int* in_sizes, int n_in,
                              void* d_out, int out_size) {
    const float* x  = (const float*)d_in[0];
    const float* wq = (const float*)d_in[1];
    const float* bq = (const float*)d_in[2];
    const float* wk = (const float*)d_in[3];
    const float* bk = (const float*)d_in[4];
    const float* wv = (const float*)d_in[5];
    const float* bv = (const float*)d_in[6];
    const float* wo = (const float*)d_in[7];
    const float* bo = (const float*)d_in[8];

    float* out = (float*)d_out;

    __half *xh, *wth, *qh, *kh, *vh, *vt, *ch;
    float *attn_scratch;
    cudaGetSymbolAddress((void**)&xh, g_xh);
    cudaGetSymbolAddress((void**)&wth, g_wth);
    cudaGetSymbolAddress((void**)&qh, g_qh);
    cudaGetSymbolAddress((void**)&kh, g_kh);
    cudaGetSymbolAddress((void**)&vh, g_vh);
    cudaGetSymbolAddress((void**)&vt, g_vt);
    cudaGetSymbolAddress((void**)&ch, g_ch);
    cudaGetSymbolAddress((void**)&attn_scratch, g_attn_scratch);

    float* attn;
    if ((size_t)out_size >= OUT_ELEMS + ATTN_ELEMS) {
        attn = out + OUT_ELEMS;
    } else if ((size_t)out_size == ATTN_ELEMS) {
        attn = out;
    } else {
        attn = attn_scratch;
    }

    __half* wqt = wth;
    __half* wkt = wth + (size_t)D_MODEL * D_MODEL;
    __half* wvt = wth + 2 * (size_t)D_MODEL * D_MODEL;
    __half* wot = wth + 3 * (size_t)D_MODEL * D_MODEL;

    const int GEMM_SMEM  = 27648 * 4;    // 110592
    const int FUSED_SMEM = 31744 * 4;    // 126976
    cudaFuncSetAttribute(gemm_h,     cudaFuncAttributeMaxDynamicSharedMemorySize, GEMM_SMEM);
    cudaFuncSetAttribute(fused_attn, cudaFuncAttributeMaxDynamicSharedMemorySize, FUSED_SMEM);

    // Preprocess
    const int XN4 = ROWS * D_MODEL / 4;
    to_half_kernel<<<XN4 / 256, 256>>>(x, xh, XN4);
    transpose_half_w<<<dim3(32, 32, 4), dim3(32, 8)>>>(wq, wk, wv, wo, wth);

    // Fused QKV projections (fp16 outputs)
    gemm_h<<<dim3(24, ROWS / 128), 256, GEMM_SMEM>>>(
        xh, wqt, wkt, wvt, bq, bk, bv, qh, kh, vh, (float*)0, 1);

    // Transpose V for the fused kernel's B operand
    transpose_v_half<<<dim3(32, 64, 2), dim3(32, 8)>>>(vh, vt);

    // Fused attention: logits + softmax + context, single attn write.
    fused_attn<<<dim3(S_LEN / 128, BH), 512, FUSED_SMEM>>>(qh, kh, vt, attn, ch);

    // Output projection (fp32 output)
    gemm_h<<<dim3(8, ROWS / 128), 256, GEMM_SMEM>>>(
        ch, wot, wot, wot, bo, bo, bo, (__half*)0, (__half*)0, (__half*)0, out, 0);
}

// round 16
// speedup vs baseline: 1.0794x; 1.0794x over previous
#include <cuda_runtime.h>
#include <cuda_fp16.h>
#include <math.h>
#include <stdint.h>

#define D_MODEL 1024
#define S_LEN   2048
#define BATCH   2
#define HEADS   16
#define DEPTH   64
#define ROWS    (BATCH * S_LEN)     // 4096
#define BH      (BATCH * HEADS)     // 32

#define OUT_ELEMS  ((size_t)ROWS * D_MODEL)
#define ATTN_ELEMS ((size_t)BH * S_LEN * S_LEN)

__device__ __half g_xh[ROWS * D_MODEL];
__device__ __half g_wth[4 * D_MODEL * D_MODEL];   // transposed fp16 weights [n][k]
__device__ __half g_qh[ROWS * D_MODEL];
__device__ __half g_kh[ROWS * D_MODEL];
__device__ __half g_vh[ROWS * D_MODEL];
__device__ __half g_ch[ROWS * D_MODEL];           // ctx fp16
__device__ float  g_attn_scratch[ATTN_ELEMS];

// ---------------------------------------------------------------------------
#define CPA(dst, src) asm volatile("cp.async.cg.shared.global [%0], [%1], 16;" :: "r"(dst), "l"(src))
#define CPC()         asm volatile("cp.async.commit_group;")
#define CPW(n)        asm volatile("cp.async.wait_group %0;" :: "n"(n))

#define LDSM_X4(r0, r1, r2, r3, addr)                                            \
    asm volatile("ldmatrix.sync.aligned.m8n8.x4.shared.b16 {%0,%1,%2,%3}, [%4];" \
                 : "=r"(r0), "=r"(r1), "=r"(r2), "=r"(r3) : "r"(addr))

#define LDSM_X4_T(r0, r1, r2, r3, addr)                                          \
    asm volatile("ldmatrix.sync.aligned.m8n8.x4.trans.shared.b16 {%0,%1,%2,%3}, [%4];" \
                 : "=r"(r0), "=r"(r1), "=r"(r2), "=r"(r3) : "r"(addr))

__device__ __forceinline__ void mma16(float* c, const uint32_t* a, const uint32_t* b) {
    asm volatile(
        "mma.sync.aligned.m16n8k16.row.col.f32.f16.f16.f32 "
        "{%0,%1,%2,%3}, {%4,%5,%6,%7}, {%8,%9}, {%0,%1,%2,%3};"
        : "+f"(c[0]), "+f"(c[1]), "+f"(c[2]), "+f"(c[3])
        : "r"(a[0]), "r"(a[1]), "r"(a[2]), "r"(a[3]), "r"(b[0]), "r"(b[1]));
}

__device__ __forceinline__ uint32_t sptr(const void* p) {
    return (uint32_t)__cvta_generic_to_shared(p);
}

// ---------------------------------------------------------------------------
__global__ void to_half_kernel(const float* __restrict__ in,
                               __half* __restrict__ out, int n4) {
    int i = blockIdx.x * blockDim.x + threadIdx.x;
    if (i < n4) {
        float4 v = ((const float4*)in)[i];
        __half2* o = (__half2*)(out + (size_t)i * 4);
        o[0] = __floats2half2_rn(v.x, v.y);
        o[1] = __floats2half2_rn(v.z, v.w);
    }
}

__global__ void transpose_half_w(const float* __restrict__ w0, const float* __restrict__ w1,
                                 const float* __restrict__ w2, const float* __restrict__ w3,
                                 __half* __restrict__ out) {
    __shared__ float tile[32][33];
    const float* in = blockIdx.z == 0 ? w0 : (blockIdx.z == 1 ? w1 :
                      (blockIdx.z == 2 ? w2 : w3));
    __half* o = out + (size_t)blockIdx.z * D_MODEL * D_MODEL;
    const int bx = blockIdx.x * 32, by = blockIdx.y * 32;
    const int tx = threadIdx.x, ty = threadIdx.y;
    #pragma unroll
    for (int i = 0; i < 32; i += 8)
        tile[ty + i][tx] = in[(size_t)(by + ty + i) * D_MODEL + bx + tx];
    __syncthreads();
    #pragma unroll
    for (int i = 0; i < 32; i += 8)
        o[(size_t)(bx + ty + i) * D_MODEL + by + tx] =
            __float2half_rn(tile[tx][ty + i]);
}

// ---------------------------------------------------------------------------
// fp16 NT GEMM + bias, up to 3 weight segments. ldmatrix fragment loads.
// BM=128 BN=128 BK=64(h), 3-stage cp.async. 8 warps (2x4), warp tile 64x32.
// ---------------------------------------------------------------------------
__global__ void __launch_bounds__(256, 2) gemm_h(
    const __half* __restrict__ A,
    const __half* __restrict__ B0, const __half* __restrict__ B1, const __half* __restrict__ B2,
    const float* __restrict__ bi0, const float* __restrict__ bi1, const float* __restrict__ bi2,
    __half* __restrict__ Ch0, __half* __restrict__ Ch1, __half* __restrict__ Ch2,
    float* __restrict__ Cf, int half_out) {
    extern __shared__ uint32_t smu[];
    uint32_t* Aw = smu;
    uint32_t* Bw = smu + 13824;

    const int sel = blockIdx.x >> 3;
    const __half* B   = sel == 0 ? B0  : (sel == 1 ? B1  : B2);
    const float* bias = sel == 0 ? bi0 : (sel == 1 ? bi1 : bi2);
    __half* Ch        = sel == 0 ? Ch0 : (sel == 1 ? Ch1 : Ch2);
    const int n0 = (blockIdx.x & 7) * 128;
    const int m0 = blockIdx.y * 128;

    const int tid = threadIdx.x, lane = tid & 31, warp = tid >> 5;
    const int wm = warp >> 2, wn = warp & 3;
    const int g = lane >> 2, tg = lane & 3;
    const int a_row = lane & 15, a_w = (lane >> 4) * 4;
    const int b_row = ((lane >> 4) << 3) + (lane & 7), b_w = ((lane >> 3) & 1) * 4;

    float acc[4][4][4] = {};

#define STAGE_G(kt, buf) {                                                       \
        _Pragma("unroll")                                                        \
        for (int i = 0; i < 4; i++) {                                            \
            int c = i * 256 + tid;                                               \
            int row = c >> 3, ch = c & 7;                                        \
            CPA(sptr(&Aw[(buf) * 4608 + row * 36 + ch * 4]),                     \
                A + (size_t)(m0 + row) * D_MODEL + (kt) + ch * 8);               \
            CPA(sptr(&Bw[(buf) * 4608 + row * 36 + ch * 4]),                     \
                B + (size_t)(n0 + row) * D_MODEL + (kt) + ch * 8);               \
        }                                                                        \
        CPC();                                                                   \
    }

    STAGE_G(0, 0);
    STAGE_G(64, 1);

    const int NT = D_MODEL / 64;
    for (int t = 0; t < NT; t++) {
        if (t + 1 < NT) { CPW(1); } else { CPW(0); }
        __syncthreads();
        if (t + 2 < NT) STAGE_G((t + 2) * 64, (t + 2) % 3);

        const uint32_t Ab = sptr(Aw + (t % 3) * 4608);
        const uint32_t Bb = sptr(Bw + (t % 3) * 4608);
        #pragma unroll
        for (int kk = 0; kk < 4; kk++) {
            const int kb = kk * 8;
            uint32_t a[4][4], b[4][2];
            #pragma unroll
            for (int mi = 0; mi < 4; mi++)
                LDSM_X4(a[mi][0], a[mi][1], a[mi][2], a[mi][3],
                        Ab + ((wm * 64 + mi * 16 + a_row) * 36 + kb + a_w) * 4);
            LDSM_X4(b[0][0], b[0][1], b[1][0], b[1][1],
                    Bb + ((wn * 32 + b_row) * 36 + kb + b_w) * 4);
            LDSM_X4(b[2][0], b[2][1], b[3][0], b[3][1],
                    Bb + ((wn * 32 + 16 + b_row) * 36 + kb + b_w) * 4);
            #pragma unroll
            for (int mi = 0; mi < 4; mi++)
                #pragma unroll
                for (int ni = 0; ni < 4; ni++)
                    mma16(acc[mi][ni], a[mi], b[ni]);
        }
    }
#undef STAGE_G

    #pragma unroll
    for (int mi = 0; mi < 4; mi++) {
        int r = m0 + wm * 64 + mi * 16 + g;
        #pragma unroll
        for (int ni = 0; ni < 4; ni++) {
            int c = n0 + wn * 32 + ni * 8 + 2 * tg;
            float b0 = bias[c], b1 = bias[c + 1];
            float v0 = acc[mi][ni][0] + b0;
            float v1 = acc[mi][ni][1] + b1;
            float v2 = acc[mi][ni][2] + b0;
            float v3 = acc[mi][ni][3] + b1;
            if (half_out) {
                *(__half2*)(Ch + (size_t)r * D_MODEL + c) = __floats2half2_rn(v0, v1);
                *(__half2*)(Ch + (size_t)(r + 8) * D_MODEL + c) = __floats2half2_rn(v2, v3);
            } else {
                *(float2*)(Cf + (size_t)r * D_MODEL + c) = make_float2(v0, v1);
                *(float2*)(Cf + (size_t)(r + 8) * D_MODEL + c) = make_float2(v2, v3);
            }
        }
    }
}

// ---------------------------------------------------------------------------
// Fused attention (fp16, recompute, ldmatrix): CTA = (bh, 128-q-strip), 512 thr.
// V consumed directly from row-major vh via ldmatrix.trans (no vt array).
// Pass 1: S=Q@K^T, rowsum of fp16(exp(S/8)) in registers.
// Pass 2: recompute S, write normalized fp32 attn from fragments, stage fp16 P
//         in smem, ctx=(P@V)*inv in registers.
// Smem (words): Qs@0 (4608) | Kbuf@4608 (2x4608) | Vbuf@13824 (2x4608) |
//               Ps@23040 (8704) | red@31744 (512).  Total 129024 B.
// ---------------------------------------------------------------------------
__global__ void __launch_bounds__(512, 1) fused_attn(
    const __half* __restrict__ q, const __half* __restrict__ kmat,
    const __half* __restrict__ v, float* __restrict__ attn,
    __half* __restrict__ ctx) {
    extern __shared__ uint32_t smu[];
    uint32_t* Qs = smu;
    float* red = (float*)(smu + 31744);

    const int bh = blockIdx.y;
    const int bb = bh >> 4, h = bh & 15;
    const __half* Qh = q    + (size_t)bb * S_LEN * D_MODEL + h * DEPTH;
    const __half* Kh = kmat + (size_t)bb * S_LEN * D_MODEL + h * DEPTH;
    const __half* Vh = v    + (size_t)bb * S_LEN * D_MODEL + h * DEPTH;
    const int q0 = blockIdx.x * 128;
    float* Ap = attn + (size_t)bh * S_LEN * S_LEN + (size_t)q0 * S_LEN;
    __half* Cp = ctx + (size_t)bb * S_LEN * D_MODEL + (size_t)q0 * D_MODEL + h * DEPTH;

    const int tid = threadIdx.x, lane = tid & 31, warp = tid >> 5;
    const int wmS = warp >> 2, wnS = warp & 3;     // 4x4, 32x32 tiles (S)
    const int wmP = warp >> 1, wnP = warp & 1;     // 8x2, 16x32 tiles (PV)
    const int g = lane >> 2, tg = lane & 3;
    const int a_row = lane & 15, a_w = (lane >> 4) * 4;
    const int b_row = ((lane >> 4) << 3) + (lane & 7), b_w = ((lane >> 3) & 1) * 4;
    // trans-LDSM lane addressing for V (B operand from [k][n] rows)
    const int vb_mat = lane >> 3;
    const int v_k  = ((vb_mat & 1) << 3) + (lane & 7);   // 0..15 within k16 chunk
    const int v_nw = (vb_mat >> 1) << 2;                 // word offset: n 0 or 8

#define STAGE_Q() {                                                              \
        _Pragma("unroll")                                                        \
        for (int i = 0; i < 2; i++) {                                            \
            int c = i * 512 + tid;                                               \
            int row = c >> 3, ch = c & 7;                                        \
            CPA(sptr(&smu[row * 36 + ch * 4]),                                   \
                Qh + (size_t)(q0 + row) * D_MODEL + ch * 8);                     \
        }                                                                        \
    }
#define STAGE_K(t, buf) {                                                        \
        uint32_t* Kb_ = smu + 4608 + (buf) * 4608;                               \
        _Pragma("unroll")                                                        \
        for (int i = 0; i < 2; i++) {                                            \
            int c = i * 512 + tid;                                               \
            int row = c >> 3, ch = c & 7;                                        \
            CPA(sptr(&Kb_[row * 36 + ch * 4]),                                   \
                Kh + (size_t)((t) * 128 + row) * D_MODEL + ch * 8);              \
        }                                                                        \
    }
#define STAGE_V(t, buf) {                                                        \
        uint32_t* Vb_ = smu + 13824 + (buf) * 4608;                              \
        _Pragma("unroll")                                                        \
        for (int i = 0; i < 2; i++) {                                            \
            int c = i * 512 + tid;                                               \
            int row = c >> 3, ch = c & 7;                                        \
            CPA(sptr(&Vb_[row * 36 + ch * 4]),                                   \
                Vh + (size_t)((t) * 128 + row) * D_MODEL + ch * 8);              \
        }                                                                        \
    }
// S-tile mma (ldmatrix): acc[2][4][4] += Q(32 rows) x K(32 cols), depth 64.
#define S_MMA(KbA, acc) {                                                        \
        _Pragma("unroll")                                                        \
        for (int kk = 0; kk < 4; kk++) {                                         \
            const int kb = kk * 8;                                               \
            uint32_t a[2][4], b[4][2];                                           \
            _Pragma("unroll")                                                    \
            for (int mi = 0; mi < 2; mi++)                                       \
                LDSM_X4(a[mi][0], a[mi][1], a[mi][2], a[mi][3],                  \
                        QsA + ((wmS * 32 + mi * 16 + a_row) * 36 + kb + a_w) * 4); \
            LDSM_X4(b[0][0], b[0][1], b[1][0], b[1][1],                          \
                    (KbA) + ((wnS * 32 + b_row) * 36 + kb + b_w) * 4);           \
            LDSM_X4(b[2][0], b[2][1], b[3][0], b[3][1],                          \
                    (KbA) + ((wnS * 32 + 16 + b_row) * 36 + kb + b_w) * 4);      \
            _Pragma("unroll")                                                    \
            for (int mi = 0; mi < 2; mi++)                                       \
                _Pragma("unroll")                                                \
                for (int ni = 0; ni < 4; ni++)                                   \
                    mma16(acc[mi][ni], a[mi], b[ni]);                            \
        }                                                                        \
    }

    const uint32_t QsA = sptr(Qs);

    // ---------------- Pass 1: row sums ----------------
    STAGE_Q(); STAGE_K(0, 0); CPC();

    float ps[4] = {0.f, 0.f, 0.f, 0.f};

    for (int t = 0; t < 16; t++) {
        CPW(0);
        __syncthreads();
        if (t + 1 < 16) { STAGE_K(t + 1, (t + 1) & 1); CPC(); }
        const uint32_t KbA = sptr(smu + 4608 + (t & 1) * 4608);

        float acc[2][4][4] = {};
        S_MMA(KbA, acc);

        #pragma unroll
        for (int mi = 0; mi < 2; mi++)
            #pragma unroll
            for (int ni = 0; ni < 4; ni++) {
                __half2 h01 = __floats2half2_rn(__expf(acc[mi][ni][0] * 0.125f),
                                                __expf(acc[mi][ni][1] * 0.125f));
                __half2 h23 = __floats2half2_rn(__expf(acc[mi][ni][2] * 0.125f),
                                                __expf(acc[mi][ni][3] * 0.125f));
                float2 f01 = __half22float2(h01);
                float2 f23 = __half22float2(h23);
                ps[mi * 2]     += f01.x + f01.y;
                ps[mi * 2 + 1] += f23.x + f23.y;
            }
        // (no trailing sync: next iteration's top barrier guards buffer reuse)
    }

    #pragma unroll
    for (int j = 0; j < 4; j++) {
        ps[j] += __shfl_xor_sync(0xffffffffu, ps[j], 1);
        ps[j] += __shfl_xor_sync(0xffffffffu, ps[j], 2);
    }
    __syncthreads();   // all S_MMA reads done before red[] written over K buffers? (red separate; barrier orders ps stores)
    if (tg == 0) {
        int rbase = wmS * 32 + g;
        red[wnS * 128 + rbase]      = ps[0];
        red[wnS * 128 + rbase + 8]  = ps[1];
        red[wnS * 128 + rbase + 16] = ps[2];
        red[wnS * 128 + rbase + 24] = ps[3];
    }
    __syncthreads();
    if (tid < 128) {
        float s = red[tid] + red[128 + tid] + red[256 + tid] + red[384 + tid];
        red[tid] = 1.0f / s;
    }
    __syncthreads();

    // ---------------- Pass 2: attn write + P@V ----------------
    uint32_t* Ps = smu + 23040;
    const uint32_t PsA = sptr(Ps);
    STAGE_K(0, 0); STAGE_V(0, 0); CPC();

    float accPV[4][4] = {};

    for (int t = 0; t < 16; t++) {
        CPW(0);
        __syncthreads();
        if (t + 1 < 16) { STAGE_K(t + 1, (t + 1) & 1); STAGE_V(t + 1, (t + 1) & 1); CPC(); }
        const uint32_t KbA = sptr(smu + 4608 + (t & 1) * 4608);
        const uint32_t VbA = sptr(smu + 13824 + (t & 1) * 4608);

        float acc[2][4][4] = {};
        S_MMA(KbA, acc);

        // exp (identical to pass 1), write normalized fp32 attn, stage fp16 P.
        #pragma unroll
        for (int mi = 0; mi < 2; mi++) {
            int r = wmS * 32 + mi * 16 + g;
            float invA = red[r], invB = red[r + 8];
            #pragma unroll
            for (int ni = 0; ni < 4; ni++) {
                __half2 h01 = __floats2half2_rn(__expf(acc[mi][ni][0] * 0.125f),
                                                __expf(acc[mi][ni][1] * 0.125f));
                __half2 h23 = __floats2half2_rn(__expf(acc[mi][ni][2] * 0.125f),
                                                __expf(acc[mi][ni][3] * 0.125f));
                float2 f01 = __half22float2(h01);
                float2 f23 = __half22float2(h23);
                int c = t * 128 + wnS * 32 + ni * 8 + 2 * tg;
                *(float2*)(Ap + (size_t)r * S_LEN + c) =
                    make_float2(f01.x * invA, f01.y * invA);
                *(float2*)(Ap + (size_t)(r + 8) * S_LEN + c) =
                    make_float2(f23.x * invB, f23.y * invB);
                Ps[r * 68 + wnS * 16 + ni * 4 + tg] = *(const uint32_t*)&h01;
                Ps[(r + 8) * 68 + wnS * 16 + ni * 4 + tg] = *(const uint32_t*)&h23;
            }
        }
        __syncthreads();   // Ps staged for cross-warp PV reads

        // PV: accPV += P_tile(128x128) @ V_tile(128x64)  (8x2 warps, 16x32)
        // V b-frags via ldmatrix.trans on row-major [k=s][n=d] smem tile.
        #pragma unroll
        for (int kk = 0; kk < 8; kk++) {
            uint32_t a[4], b[4][2];
            LDSM_X4(a[0], a[1], a[2], a[3],
                    PsA + ((wmP * 16 + a_row) * 68 + kk * 8 + a_w) * 4);
            LDSM_X4_T(b[0][0], b[0][1], b[1][0], b[1][1],
                      VbA + ((kk * 16 + v_k) * 36 + wnP * 16 + v_nw) * 4);
            LDSM_X4_T(b[2][0], b[2][1], b[3][0], b[3][1],
                      VbA + ((kk * 16 + v_k) * 36 + wnP * 16 + 8 + v_nw) * 4);
            #pragma unroll
            for (int ni = 0; ni < 4; ni++)
                mma16(accPV[ni], a, b[ni]);
        }
        // (no trailing sync: next iteration's top barrier guards Ps/V reuse)
    }

    // Epilogue: ctx = accPV * inv -> fp16.
    {
        int rp = wmP * 16 + g;
        float invA = red[rp], invB = red[rp + 8];
        #pragma unroll
        for (int ni = 0; ni < 4; ni++) {
            int c = wnP * 32 + ni * 8 + 2 * tg;
            *(__half2*)(Cp + (size_t)rp * D_MODEL + c) =
                __floats2half2_rn(accPV[ni][0] * invA, accPV[ni][1] * invA);
            *(__half2*)(Cp + (size_t)(rp + 8) * D_MODEL + c) =
                __floats2half2_rn(accPV[ni][2] * invB, accPV[ni][3] * invB);
        }
    }
#undef STAGE_Q
#undef STAGE_K
#undef STAGE_V
#undef S_MMA
}

// ---------------------------------------------------------------------------
extern "C" void kernel_launch(void* const* d_in, const int* in_sizes, int n_in,
                              void* d_out, int out_size) {
    const float* x  = (const float*)d_in[0];
    const float* wq = (const float*)d_in[1];
    const float* bq = (const float*)d_in[2];
    const float* wk = (const float*)d_in[3];
    const float* bk = (const float*)d_in[4];
    const float* wv = (const float*)d_in[5];
    const float* bv = (const float*)d_in[6];
    const float* wo = (const float*)d_in[7];
    const float* bo = (const float*)d_in[8];

    float* out = (float*)d_out;

    __half *xh, *wth, *qh, *kh, *vh, *ch;
    float *attn_scratch;
    cudaGetSymbolAddress((void**)&xh, g_xh);
    cudaGetSymbolAddress((void**)&wth, g_wth);
    cudaGetSymbolAddress((void**)&qh, g_qh);
    cudaGetSymbolAddress((void**)&kh, g_kh);
    cudaGetSymbolAddress((void**)&vh, g_vh);
    cudaGetSymbolAddress((void**)&ch, g_ch);
    cudaGetSymbolAddress((void**)&attn_scratch, g_attn_scratch);

    float* attn;
    if ((size_t)out_size >= OUT_ELEMS + ATTN_ELEMS) {
        attn = out + OUT_ELEMS;
    } else if ((size_t)out_size == ATTN_ELEMS) {
        attn = out;
    } else {
        attn = attn_scratch;
    }

    __half* wqt = wth;
    __half* wkt = wth + (size_t)D_MODEL * D_MODEL;
    __half* wvt = wth + 2 * (size_t)D_MODEL * D_MODEL;
    __half* wot = wth + 3 * (size_t)D_MODEL * D_MODEL;

    const int GEMM_SMEM  = 27648 * 4;    // 110592
    const int FUSED_SMEM = 32256 * 4;    // 129024
    cudaFuncSetAttribute(gemm_h,     cudaFuncAttributeMaxDynamicSharedMemorySize, GEMM_SMEM);
    cudaFuncSetAttribute(fused_attn, cudaFuncAttributeMaxDynamicSharedMemorySize, FUSED_SMEM);

    // Preprocess
    const int XN4 = ROWS * D_MODEL / 4;
    to_half_kernel<<<XN4 / 256, 256>>>(x, xh, XN4);
    transpose_half_w<<<dim3(32, 32, 4), dim3(32, 8)>>>(wq, wk, wv, wo, wth);

    // Fused QKV projections (fp16 outputs)
    gemm_h<<<dim3(24, ROWS / 128), 256, GEMM_SMEM>>>(
        xh, wqt, wkt, wvt, bq, bk, bv, qh, kh, vh, (float*)0, 1);

    // Fused attention: logits + softmax + context, single attn write.
    fused_attn<<<dim3(S_LEN / 128, BH), 512, FUSED_SMEM>>>(qh, kh, vh, attn, ch);

    // Output projection (fp32 output)
    gemm_h<<<dim3(8, ROWS / 128), 256, GEMM_SMEM>>>(
        ch, wot, wot, wot, bo, bo, bo, (__half*)0, (__half*)0, (__half*)0, out, 0);
}

// round 17
// speedup vs baseline: 1.2064x; 1.1177x over previous
#include <cuda_runtime.h>
#include <cuda_fp16.h>
#include <math.h>
#include <stdint.h>

#define D_MODEL 1024
#define S_LEN   2048
#define BATCH   2
#define HEADS   16
#define DEPTH   64
#define ROWS    (BATCH * S_LEN)     // 4096
#define BH      (BATCH * HEADS)     // 32

#define OUT_ELEMS  ((size_t)ROWS * D_MODEL)
#define ATTN_ELEMS ((size_t)BH * S_LEN * S_LEN)

__device__ __half g_xh[ROWS * D_MODEL];
__device__ __half g_wth[4 * D_MODEL * D_MODEL];   // transposed fp16 weights [n][k]
__device__ __half g_qh[ROWS * D_MODEL];
__device__ __half g_kh[ROWS * D_MODEL];
__device__ __half g_vh[ROWS * D_MODEL];
__device__ __half g_ch[ROWS * D_MODEL];           // ctx fp16
__device__ float  g_attn_scratch[ATTN_ELEMS];

// ---------------------------------------------------------------------------
#define CPA(dst, src) asm volatile("cp.async.cg.shared.global [%0], [%1], 16;" :: "r"(dst), "l"(src))
#define CPC()         asm volatile("cp.async.commit_group;")
#define CPW(n)        asm volatile("cp.async.wait_group %0;" :: "n"(n))

#define LDSM_X4(r0, r1, r2, r3, addr)                                            \
    asm volatile("ldmatrix.sync.aligned.m8n8.x4.shared.b16 {%0,%1,%2,%3}, [%4];" \
                 : "=r"(r0), "=r"(r1), "=r"(r2), "=r"(r3) : "r"(addr))

#define LDSM_X4_T(r0, r1, r2, r3, addr)                                          \
    asm volatile("ldmatrix.sync.aligned.m8n8.x4.trans.shared.b16 {%0,%1,%2,%3}, [%4];" \
                 : "=r"(r0), "=r"(r1), "=r"(r2), "=r"(r3) : "r"(addr))

__device__ __forceinline__ void mma16(float* c, const uint32_t* a, const uint32_t* b) {
    asm volatile(
        "mma.sync.aligned.m16n8k16.row.col.f32.f16.f16.f32 "
        "{%0,%1,%2,%3}, {%4,%5,%6,%7}, {%8,%9}, {%0,%1,%2,%3};"
        : "+f"(c[0]), "+f"(c[1]), "+f"(c[2]), "+f"(c[3])
        : "r"(a[0]), "r"(a[1]), "r"(a[2]), "r"(a[3]), "r"(b[0]), "r"(b[1]));
}

__device__ __forceinline__ uint32_t sptr(const void* p) {
    return (uint32_t)__cvta_generic_to_shared(p);
}

__device__ __forceinline__ void stcs2(float* p, float x, float y) {
    asm volatile("st.global.cs.v2.f32 [%0], {%1, %2};" :: "l"(p), "f"(x), "f"(y) : "memory");
}

// ---------------------------------------------------------------------------
__global__ void to_half_kernel(const float* __restrict__ in,
                               __half* __restrict__ out, int n4) {
    int i = blockIdx.x * blockDim.x + threadIdx.x;
    if (i < n4) {
        float4 v = ((const float4*)in)[i];
        __half2* o = (__half2*)(out + (size_t)i * 4);
        o[0] = __floats2half2_rn(v.x, v.y);
        o[1] = __floats2half2_rn(v.z, v.w);
    }
}

__global__ void transpose_half_w(const float* __restrict__ w0, const float* __restrict__ w1,
                                 const float* __restrict__ w2, const float* __restrict__ w3,
                                 __half* __restrict__ out) {
    __shared__ float tile[32][33];
    const float* in = blockIdx.z == 0 ? w0 : (blockIdx.z == 1 ? w1 :
                      (blockIdx.z == 2 ? w2 : w3));
    __half* o = out + (size_t)blockIdx.z * D_MODEL * D_MODEL;
    const int bx = blockIdx.x * 32, by = blockIdx.y * 32;
    const int tx = threadIdx.x, ty = threadIdx.y;
    #pragma unroll
    for (int i = 0; i < 32; i += 8)
        tile[ty + i][tx] = in[(size_t)(by + ty + i) * D_MODEL + bx + tx];
    __syncthreads();
    #pragma unroll
    for (int i = 0; i < 32; i += 8)
        o[(size_t)(bx + ty + i) * D_MODEL + by + tx] =
            __float2half_rn(tile[tx][ty + i]);
}

// ---------------------------------------------------------------------------
// fp16 NT GEMM + bias, up to 3 weight segments. (R16 known-good)
// ---------------------------------------------------------------------------
__global__ void __launch_bounds__(256, 2) gemm_h(
    const __half* __restrict__ A,
    const __half* __restrict__ B0, const __half* __restrict__ B1, const __half* __restrict__ B2,
    const float* __restrict__ bi0, const float* __restrict__ bi1, const float* __restrict__ bi2,
    __half* __restrict__ Ch0, __half* __restrict__ Ch1, __half* __restrict__ Ch2,
    float* __restrict__ Cf, int half_out) {
    extern __shared__ uint32_t smu[];
    uint32_t* Aw = smu;
    uint32_t* Bw = smu + 13824;

    const int sel = blockIdx.x >> 3;
    const __half* B   = sel == 0 ? B0  : (sel == 1 ? B1  : B2);
    const float* bias = sel == 0 ? bi0 : (sel == 1 ? bi1 : bi2);
    __half* Ch        = sel == 0 ? Ch0 : (sel == 1 ? Ch1 : Ch2);
    const int n0 = (blockIdx.x & 7) * 128;
    const int m0 = blockIdx.y * 128;

    const int tid = threadIdx.x, lane = tid & 31, warp = tid >> 5;
    const int wm = warp >> 2, wn = warp & 3;
    const int g = lane >> 2, tg = lane & 3;
    const int a_row = lane & 15, a_w = (lane >> 4) * 4;
    const int b_row = ((lane >> 4) << 3) + (lane & 7), b_w = ((lane >> 3) & 1) * 4;

    float acc[4][4][4] = {};

#define STAGE_G(kt, buf) {                                                       \
        _Pragma("unroll")                                                        \
        for (int i = 0; i < 4; i++) {                                            \
            int c = i * 256 + tid;                                               \
            int row = c >> 3, ch = c & 7;                                        \
            CPA(sptr(&Aw[(buf) * 4608 + row * 36 + ch * 4]),                     \
                A + (size_t)(m0 + row) * D_MODEL + (kt) + ch * 8);               \
            CPA(sptr(&Bw[(buf) * 4608 + row * 36 + ch * 4]),                     \
                B + (size_t)(n0 + row) * D_MODEL + (kt) + ch * 8);               \
        }                                                                        \
        CPC();                                                                   \
    }

    STAGE_G(0, 0);
    STAGE_G(64, 1);

    const int NT = D_MODEL / 64;
    for (int t = 0; t < NT; t++) {
        if (t + 1 < NT) { CPW(1); } else { CPW(0); }
        __syncthreads();
        if (t + 2 < NT) STAGE_G((t + 2) * 64, (t + 2) % 3);

        const uint32_t Ab = sptr(Aw + (t % 3) * 4608);
        const uint32_t Bb = sptr(Bw + (t % 3) * 4608);
        #pragma unroll
        for (int kk = 0; kk < 4; kk++) {
            const int kb = kk * 8;
            uint32_t a[4][4], b[4][2];
            #pragma unroll
            for (int mi = 0; mi < 4; mi++)
                LDSM_X4(a[mi][0], a[mi][1], a[mi][2], a[mi][3],
                        Ab + ((wm * 64 + mi * 16 + a_row) * 36 + kb + a_w) * 4);
            LDSM_X4(b[0][0], b[0][1], b[1][0], b[1][1],
                    Bb + ((wn * 32 + b_row) * 36 + kb + b_w) * 4);
            LDSM_X4(b[2][0], b[2][1], b[3][0], b[3][1],
                    Bb + ((wn * 32 + 16 + b_row) * 36 + kb + b_w) * 4);
            #pragma unroll
            for (int mi = 0; mi < 4; mi++)
                #pragma unroll
                for (int ni = 0; ni < 4; ni++)
                    mma16(acc[mi][ni], a[mi], b[ni]);
        }
    }
#undef STAGE_G

    #pragma unroll
    for (int mi = 0; mi < 4; mi++) {
        int r = m0 + wm * 64 + mi * 16 + g;
        #pragma unroll
        for (int ni = 0; ni < 4; ni++) {
            int c = n0 + wn * 32 + ni * 8 + 2 * tg;
            float b0 = bias[c], b1 = bias[c + 1];
            float v0 = acc[mi][ni][0] + b0;
            float v1 = acc[mi][ni][1] + b1;
            float v2 = acc[mi][ni][2] + b0;
            float v3 = acc[mi][ni][3] + b1;
            if (half_out) {
                *(__half2*)(Ch + (size_t)r * D_MODEL + c) = __floats2half2_rn(v0, v1);
                *(__half2*)(Ch + (size_t)(r + 8) * D_MODEL + c) = __floats2half2_rn(v2, v3);
            } else {
                *(float2*)(Cf + (size_t)r * D_MODEL + c) = make_float2(v0, v1);
                *(float2*)(Cf + (size_t)(r + 8) * D_MODEL + c) = make_float2(v2, v3);
            }
        }
    }
}

// ---------------------------------------------------------------------------
// Fused attention v3: 64-row q-strip, 256 threads, 2 CTAs/SM.
// Pass 1: S=Q@K^T (16 tiles of 128), rowsum of RAW exp(S/8) in registers.
// Pass 2: recompute S, write normalized fp32 attn (streaming stores), stage
//         fp16 P in smem, ctx=(P@V)*inv. V via trans-LDSM from row-major.
// Smem (words): Qs@0 (2304) | K@2304 (2x4608) | V@11520 (2x4608) |
//               Ps@20736 (4352) | red@25088 (256).  Total 101376 B.
// ---------------------------------------------------------------------------
__global__ void __launch_bounds__(256, 2) fused_attn(
    const __half* __restrict__ q, const __half* __restrict__ kmat,
    const __half* __restrict__ v, float* __restrict__ attn,
    __half* __restrict__ ctx) {
    extern __shared__ uint32_t smu[];
    float* red = (float*)(smu + 25088);

    const int bh = blockIdx.y;
    const int bb = bh >> 4, h = bh & 15;
    const __half* Qh = q    + (size_t)bb * S_LEN * D_MODEL + h * DEPTH;
    const __half* Kh = kmat + (size_t)bb * S_LEN * D_MODEL + h * DEPTH;
    const __half* Vh = v    + (size_t)bb * S_LEN * D_MODEL + h * DEPTH;
    const int q0 = blockIdx.x * 64;
    float* Ap = attn + (size_t)bh * S_LEN * S_LEN + (size_t)q0 * S_LEN;
    __half* Cp = ctx + (size_t)bb * S_LEN * D_MODEL + (size_t)q0 * D_MODEL + h * DEPTH;

    const int tid = threadIdx.x, lane = tid & 31, warp = tid >> 5;
    const int wmS = warp >> 2, wnS = warp & 3;     // 2x4; S warp tile 32x32
    const int wmP = warp >> 1, wnP = warp & 1;     // 4x2; PV warp tile 16x32
    const int g = lane >> 2, tg = lane & 3;
    const int a_row = lane & 15, a_w = (lane >> 4) * 4;
    const int b_row = ((lane >> 4) << 3) + (lane & 7), b_w = ((lane >> 3) & 1) * 4;
    const int vb_mat = lane >> 3;
    const int v_k  = ((vb_mat & 1) << 3) + (lane & 7);
    const int v_nw = (vb_mat >> 1) << 2;

#define STAGE_Q() {                                                              \
        _Pragma("unroll")                                                        \
        for (int i = 0; i < 2; i++) {                                            \
            int c = i * 256 + tid;                                               \
            int row = c >> 3, ch = c & 7;                                        \
            CPA(sptr(&smu[row * 36 + ch * 4]),                                   \
                Qh + (size_t)(q0 + row) * D_MODEL + ch * 8);                     \
        }                                                                        \
    }
#define STAGE_K(t, buf) {                                                        \
        uint32_t* Kb_ = smu + 2304 + (buf) * 4608;                               \
        _Pragma("unroll")                                                        \
        for (int i = 0; i < 4; i++) {                                            \
            int c = i * 256 + tid;                                               \
            int row = c >> 3, ch = c & 7;                                        \
            CPA(sptr(&Kb_[row * 36 + ch * 4]),                                   \
                Kh + (size_t)((t) * 128 + row) * D_MODEL + ch * 8);              \
        }                                                                        \
    }
#define STAGE_V(t, buf) {                                                        \
        uint32_t* Vb_ = smu + 11520 + (buf) * 4608;                              \
        _Pragma("unroll")                                                        \
        for (int i = 0; i < 4; i++) {                                            \
            int c = i * 256 + tid;                                               \
            int row = c >> 3, ch = c & 7;                                        \
            CPA(sptr(&Vb_[row * 36 + ch * 4]),                                   \
                Vh + (size_t)((t) * 128 + row) * D_MODEL + ch * 8);              \
        }                                                                        \
    }
// S-tile mma: acc[2][4][4] += Q(warp 32 rows of 64) x K(warp 32 cols of 128).
#define S_MMA(KbA, acc) {                                                        \
        _Pragma("unroll")                                                        \
        for (int kk = 0; kk < 4; kk++) {                                         \
            const int kb = kk * 8;                                               \
            uint32_t a[2][4], b[4][2];                                           \
            _Pragma("unroll")                                                    \
            for (int mi = 0; mi < 2; mi++)                                       \
                LDSM_X4(a[mi][0], a[mi][1], a[mi][2], a[mi][3],                  \
                        QsA + ((wmS * 32 + mi * 16 + a_row) * 36 + kb + a_w) * 4); \
            LDSM_X4(b[0][0], b[0][1], b[1][0], b[1][1],                          \
                    (KbA) + ((wnS * 32 + b_row) * 36 + kb + b_w) * 4);           \
            LDSM_X4(b[2][0], b[2][1], b[3][0], b[3][1],                          \
                    (KbA) + ((wnS * 32 + 16 + b_row) * 36 + kb + b_w) * 4);      \
            _Pragma("unroll")                                                    \
            for (int mi = 0; mi < 2; mi++)                                       \
                _Pragma("unroll")                                                \
                for (int ni = 0; ni < 4; ni++)                                   \
                    mma16(acc[mi][ni], a[mi], b[ni]);                            \
        }                                                                        \
    }

    const uint32_t QsA = sptr(smu);

    // ---------------- Pass 1: row sums of raw exp ----------------
    STAGE_Q(); STAGE_K(0, 0); CPC();

    float ps[4] = {0.f, 0.f, 0.f, 0.f};

    for (int t = 0; t < 16; t++) {
        CPW(0);
        __syncthreads();
        if (t + 1 < 16) { STAGE_K(t + 1, (t + 1) & 1); CPC(); }
        const uint32_t KbA = sptr(smu + 2304 + (t & 1) * 4608);

        float acc[2][4][4] = {};
        S_MMA(KbA, acc);

        #pragma unroll
        for (int mi = 0; mi < 2; mi++)
            #pragma unroll
            for (int ni = 0; ni < 4; ni++) {
                ps[mi * 2]     += __expf(acc[mi][ni][0] * 0.125f)
                                + __expf(acc[mi][ni][1] * 0.125f);
                ps[mi * 2 + 1] += __expf(acc[mi][ni][2] * 0.125f)
                                + __expf(acc[mi][ni][3] * 0.125f);
            }
    }

    #pragma unroll
    for (int j = 0; j < 4; j++) {
        ps[j] += __shfl_xor_sync(0xffffffffu, ps[j], 1);
        ps[j] += __shfl_xor_sync(0xffffffffu, ps[j], 2);
    }
    __syncthreads();
    if (tg == 0) {
        int rbase = wmS * 32 + g;
        red[wnS * 64 + rbase]      = ps[0];
        red[wnS * 64 + rbase + 8]  = ps[1];
        red[wnS * 64 + rbase + 16] = ps[2];
        red[wnS * 64 + rbase + 24] = ps[3];
    }
    __syncthreads();
    if (tid < 64) {
        float s = red[tid] + red[64 + tid] + red[128 + tid] + red[192 + tid];
        red[tid] = 1.0f / s;
    }
    __syncthreads();

    // ---------------- Pass 2: attn write + P@V ----------------
    uint32_t* Ps = smu + 20736;
    const uint32_t PsA = sptr(Ps);
    STAGE_K(0, 0); STAGE_V(0, 0); CPC();

    float accPV[4][4] = {};

    for (int t = 0; t < 16; t++) {
        CPW(0);
        __syncthreads();
        if (t + 1 < 16) { STAGE_K(t + 1, (t + 1) & 1); STAGE_V(t + 1, (t + 1) & 1); CPC(); }
        const uint32_t KbA = sptr(smu + 2304 + (t & 1) * 4608);
        const uint32_t VbA = sptr(smu + 11520 + (t & 1) * 4608);

        float acc[2][4][4] = {};
        S_MMA(KbA, acc);

        // exp -> fp16 P; write normalized fp32 attn (streaming); stage P.
        #pragma unroll
        for (int mi = 0; mi < 2; mi++) {
            int r = wmS * 32 + mi * 16 + g;
            float invA = red[r], invB = red[r + 8];
            #pragma unroll
            for (int ni = 0; ni < 4; ni++) {
                __half2 h01 = __floats2half2_rn(__expf(acc[mi][ni][0] * 0.125f),
                                                __expf(acc[mi][ni][1] * 0.125f));
                __half2 h23 = __floats2half2_rn(__expf(acc[mi][ni][2] * 0.125f),
                                                __expf(acc[mi][ni][3] * 0.125f));
                float2 f01 = __half22float2(h01);
                float2 f23 = __half22float2(h23);
                int c = t * 128 + wnS * 32 + ni * 8 + 2 * tg;
                stcs2(Ap + (size_t)r * S_LEN + c, f01.x * invA, f01.y * invA);
                stcs2(Ap + (size_t)(r + 8) * S_LEN + c, f23.x * invB, f23.y * invB);
                Ps[r * 68 + wnS * 16 + ni * 4 + tg] = *(const uint32_t*)&h01;
                Ps[(r + 8) * 68 + wnS * 16 + ni * 4 + tg] = *(const uint32_t*)&h23;
            }
        }
        __syncthreads();   // Ps staged for cross-warp PV reads

        // PV: accPV += P_tile(64x128) @ V_tile(128x64)  (4x2 warps, 16x32)
        #pragma unroll
        for (int kk = 0; kk < 8; kk++) {
            uint32_t a[4], b[4][2];
            LDSM_X4(a[0], a[1], a[2], a[3],
                    PsA + ((wmP * 16 + a_row) * 68 + kk * 8 + a_w) * 4);
            LDSM_X4_T(b[0][0], b[0][1], b[1][0], b[1][1],
                      VbA + ((kk * 16 + v_k) * 36 + wnP * 16 + v_nw) * 4);
            LDSM_X4_T(b[2][0], b[2][1], b[3][0], b[3][1],
                      VbA + ((kk * 16 + v_k) * 36 + wnP * 16 + 8 + v_nw) * 4);
            #pragma unroll
            for (int ni = 0; ni < 4; ni++)
                mma16(accPV[ni], a, b[ni]);
        }
    }

    // Epilogue: ctx = accPV * inv -> fp16.
    {
        int rp = wmP * 16 + g;
        float invA = red[rp], invB = red[rp + 8];
        #pragma unroll
        for (int ni = 0; ni < 4; ni++) {
            int c = wnP * 32 + ni * 8 + 2 * tg;
            *(__half2*)(Cp + (size_t)rp * D_MODEL + c) =
                __floats2half2_rn(accPV[ni][0] * invA, accPV[ni][1] * invA);
            *(__half2*)(Cp + (size_t)(rp + 8) * D_MODEL + c) =
                __floats2half2_rn(accPV[ni][2] * invB, accPV[ni][3] * invB);
        }
    }
#undef STAGE_Q
#undef STAGE_K
#undef STAGE_V
#undef S_MMA
}

// ---------------------------------------------------------------------------
extern "C" void kernel_launch(void* const* d_in, const int* in_sizes, int n_in,
                              void* d_out, int out_size) {
    const float* x  = (const float*)d_in[0];
    const float* wq = (const float*)d_in[1];
    const float* bq = (const float*)d_in[2];
    const float* wk = (const float*)d_in[3];
    const float* bk = (const float*)d_in[4];
    const float* wv = (const float*)d_in[5];
    const float* bv = (const float*)d_in[6];
    const float* wo = (const float*)d_in[7];
    const float* bo = (const float*)d_in[8];

    float* out = (float*)d_out;

    __half *xh, *wth, *qh, *kh, *vh, *ch;
    float *attn_scratch;
    cudaGetSymbolAddress((void**)&xh, g_xh);
    cudaGetSymbolAddress((void**)&wth, g_wth);
    cudaGetSymbolAddress((void**)&qh, g_qh);
    cudaGetSymbolAddress((void**)&kh, g_kh);
    cudaGetSymbolAddress((void**)&vh, g_vh);
    cudaGetSymbolAddress((void**)&ch, g_ch);
    cudaGetSymbolAddress((void**)&attn_scratch, g_attn_scratch);

    float* attn;
    if ((size_t)out_size >= OUT_ELEMS + ATTN_ELEMS) {
        attn = out + OUT_ELEMS;
    } else if ((size_t)out_size == ATTN_ELEMS) {
        attn = out;
    } else {
        attn = attn_scratch;
    }

    __half* wqt = wth;
    __half* wkt = wth + (size_t)D_MODEL * D_MODEL;
    __half* wvt = wth + 2 * (size_t)D_MODEL * D_MODEL;
    __half* wot = wth + 3 * (size_t)D_MODEL * D_MODEL;

    const int GEMM_SMEM  = 27648 * 4;    // 110592
    const int FUSED_SMEM = 25344 * 4;    // 101376
    cudaFuncSetAttribute(gemm_h,     cudaFuncAttributeMaxDynamicSharedMemorySize, GEMM_SMEM);
    cudaFuncSetAttribute(fused_attn, cudaFuncAttributeMaxDynamicSharedMemorySize, FUSED_SMEM);

    // Preprocess
    const int XN4 = ROWS * D_MODEL / 4;
    to_half_kernel<<<XN4 / 256, 256>>>(x, xh, XN4);
    transpose_half_w<<<dim3(32, 32, 4), dim3(32, 8)>>>(wq, wk, wv, wo, wth);

    // Fused QKV projections (fp16 outputs)
    gemm_h<<<dim3(24, ROWS / 128), 256, GEMM_SMEM>>>(
        xh, wqt, wkt, wvt, bq, bk, bv, qh, kh, vh, (float*)0, 1);

    // Fused attention: 64-row strips, 2 CTAs/SM.
    fused_attn<<<dim3(S_LEN / 64, BH), 256, FUSED_SMEM>>>(qh, kh, vh, attn, ch);

    // Output projection (fp32 output)
    gemm_h<<<dim3(8, ROWS / 128), 256, GEMM_SMEM>>>(
        ch, wot, wot, wot, bo, bo, bo, (__half*)0, (__half*)0, (__half*)0, out, 0);
}